// round 16
// baseline (speedup 1.0000x reference)
#include <cuda_runtime.h>
#include <cuda_bf16.h>
#include <cuda_fp16.h>
#include <math.h>
#include <stdint.h>

#define NN 100000
#define EE 1000000
#define INF 128
#define HH 64
#define BN_EPS 1e-5f
#define NB_BUILD 98
#define AGG_BLOCKS 592   // 148 SMs * 4 resident blocks

typedef unsigned long long ull;

// ---------------- scratch (device globals, no runtime alloc) ----------------
// Invariant: g_indeg is all-zero at every kernel_launch entry (zero-initialized at
// module load; build kernel re-zeros it after use on every execution).
// g_bar1 / g_ticket / g_flag are MONOTONIC (generation = value/NB_BUILD).
__device__ int   g_indeg[NN];
__device__ uint2 g_offcnt[NN];     // {csr offset, indegree}
__device__ int   g_rank[EE];
__device__ int   g_csr[EE];
__device__ float g_dinv[NN];
__device__ int   g_bsum[NB_BUILD];
__device__ int   g_boff[NB_BUILD];
__device__ int   g_bar1;
__device__ int   g_ticket;
__device__ int   g_flag;
__device__ float g_sum[2][HH];
__device__ float g_sq[2][HH];

__device__ __half2 g_h[(size_t)NN * 32];   // GEMM output (fp16 pairs), pre-scaled by dinv[row]
__device__ float   g_agg[(size_t)NN * HH]; // aggregation output (pre-BN, fp32)

// packed dual-fp32 ops (Blackwell; ptxas never emits these from C++)
__device__ __forceinline__ ull add2(ull a, ull b) {
    ull d;
    asm("add.rn.f32x2 %0, %1, %2;" : "=l"(d) : "l"(a), "l"(b));
    return d;
}
__device__ __forceinline__ ull fma2(ull a, ull b, ull c) {
    ull d;
    asm("fma.rn.f32x2 %0, %1, %2, %3;" : "=l"(d) : "l"(a), "l"(b), "l"(c));
    return d;
}
__device__ __forceinline__ uint32_t hadd2u(uint32_t a, uint32_t b) {
    __half2 r = __hadd2(*reinterpret_cast<__half2*>(&a), *reinterpret_cast<__half2*>(&b));
    return *reinterpret_cast<uint32_t*>(&r);
}
__device__ __forceinline__ ull cvt2(uint32_t hh) {   // half2 -> packed float2
    float2 f = __half22float2(*reinterpret_cast<__half2*>(&hh));
    return *reinterpret_cast<ull*>(&f);
}

// ---------------- fused graph build: hist + device barrier + scan ----------------
__global__ __launch_bounds__(1024, 1)
void build_kernel(const int* __restrict__ dst) {
    __shared__ int sh[1024];
    __shared__ int sh_tgt;
    __shared__ int sh_gen;
    __shared__ int amLast;
    int t = threadIdx.x;
    int b = blockIdx.x;

    if (b == 0 && t < 2 * HH) {
        ((float*)g_sum)[t] = 0.f;
        ((float*)g_sq)[t]  = 0.f;
    }

    // ---- phase 1: histogram + per-edge rank (grid-stride) ----
    for (int e = b * 1024 + t; e < EE; e += NB_BUILD * 1024)
        g_rank[e] = atomicAdd(&g_indeg[dst[e]], 1);

    // ---- device-wide barrier (monotonic generation counter) ----
    __syncthreads();
    if (t == 0) {
        __threadfence();
        int my = atomicAdd(&g_bar1, 1);
        sh_tgt = (my / NB_BUILD + 1) * NB_BUILD;
    }
    __syncthreads();
    if (t == 0) {
        while (atomicAdd(&g_bar1, 0) < sh_tgt) {}
    }
    __syncthreads();

    // ---- phase 2: block-local inclusive scan of indeg ----
    int idx = b * 1024 + t;
    int v = (idx < NN) ? g_indeg[idx] : 0;
    sh[t] = v;
    __syncthreads();
    for (int o = 1; o < 1024; o <<= 1) {
        int a = (t >= o) ? sh[t - o] : 0;
        __syncthreads();
        sh[t] += a;
        __syncthreads();
    }
    int incl = sh[t];
    if (t == 1023) {
        g_bsum[b] = incl;
        __threadfence();
        int my = atomicAdd(&g_ticket, 1);
        amLast = ((my % NB_BUILD) == NB_BUILD - 1);
        sh_gen = my / NB_BUILD;
    }
    __syncthreads();
    int gen = sh_gen;
    if (amLast) {
        int bv = (t < NB_BUILD) ? g_bsum[t] : 0;
        sh[t] = (t < 128) ? bv : 0;
        __syncthreads();
        for (int o = 1; o < 128; o <<= 1) {
            int a = (t >= o && t < 128) ? sh[t - o] : 0;
            __syncthreads();
            if (t < 128) sh[t] += a;
            __syncthreads();
        }
        if (t < NB_BUILD) g_boff[t] = sh[t] - bv;
        __threadfence();
        if (t == 0) atomicAdd(&g_flag, 1);
    }
    if (t == 0) {
        while (atomicAdd(&g_flag, 0) < gen + 1) {}
    }
    __syncthreads();
    if (idx < NN) {
        int off = g_boff[b] + incl - v;
        g_offcnt[idx] = make_uint2((unsigned)off, (unsigned)v);
        g_dinv[idx] = rsqrtf((float)(v + 1));   // deg = indeg + self-loop (GEMM epilogue)
        g_indeg[idx] = 0;                        // self-clean for next call
    }
}

// ---------------- HMMA GEMM (mma.sync m16n8k16, fp16 in / fp32 accum) ----------------

__device__ __forceinline__ uint32_t smem_u32(const void* p) {
    uint32_t a;
    asm("{ .reg .u64 t; cvta.to.shared.u64 t, %1; cvt.u32.u64 %0, t; }" : "=r"(a) : "l"(p));
    return a;
}

__device__ __forceinline__ void ldmat_x4(uint32_t& r0, uint32_t& r1, uint32_t& r2, uint32_t& r3,
                                         uint32_t addr) {
    asm volatile("ldmatrix.sync.aligned.m8n8.x4.shared.b16 {%0,%1,%2,%3}, [%4];"
                 : "=r"(r0), "=r"(r1), "=r"(r2), "=r"(r3) : "r"(addr));
}

__device__ __forceinline__ void mma_16816(float& c0, float& c1, float& c2, float& c3,
                                          uint32_t a0, uint32_t a1, uint32_t a2, uint32_t a3,
                                          uint32_t b0, uint32_t b1) {
    asm volatile("mma.sync.aligned.m16n8k16.row.col.f32.f16.f16.f32 "
                 "{%0,%1,%2,%3}, {%4,%5,%6,%7}, {%8,%9}, {%0,%1,%2,%3};"
                 : "+f"(c0), "+f"(c1), "+f"(c2), "+f"(c3)
                 : "r"(a0), "r"(a1), "r"(a2), "r"(a3), "r"(b0), "r"(b1));
}

template <int K, int DO_BN, int DO_FILL>
__global__ __launch_bounds__(256, 4)
void mma_gemm_kernel(const float* __restrict__ A, const float* __restrict__ W,
                     __half2* __restrict__ C,
                     const float* __restrict__ gamma, const float* __restrict__ beta,
                     const int* __restrict__ src, const int* __restrict__ dst) {
    extern __shared__ char smem[];
    const int KS = K + 8;
    const int A_OFF = 512;
    const int B_OFF = A_OFF + 128 * KS * 2;
    float* s_scale = (float*)(smem + 0);
    float* s_shift = (float*)(smem + 256);
    __half* As = (__half*)(smem + A_OFF);
    __half* Bs = (__half*)(smem + B_OFF);

    int t = threadIdx.x;
    int wid = t >> 5;
    int lane = t & 31;
    int m0 = blockIdx.x * 128;

    if (DO_BN) {
        if (t < 64) {
            float m   = g_sum[0][t] * (1.0f / NN);
            float var = g_sq[0][t] * (1.0f / NN) - m * m;
            float sc  = gamma[t] * rsqrtf(var + BN_EPS);
            s_scale[t] = sc;
            s_shift[t] = beta[t] - m * sc;
        }
        __syncthreads();
    }

    // ---- A tile: fp32 -> (BN+ReLU) -> fp16 ----
    const int QK = K / 4;
    for (int idx = t; idx < 128 * QK; idx += 256) {
        int r = idx / QK;
        int q = idx - r * QK;
        int k = q * 4;
        int row = m0 + r;
        float4 v = make_float4(0.f, 0.f, 0.f, 0.f);
        if (row < NN) v = *reinterpret_cast<const float4*>(A + (size_t)row * K + k);
        if (DO_BN) {
            v.x = fmaxf(fmaf(v.x, s_scale[k + 0], s_shift[k + 0]), 0.f);
            v.y = fmaxf(fmaf(v.y, s_scale[k + 1], s_shift[k + 1]), 0.f);
            v.z = fmaxf(fmaf(v.z, s_scale[k + 2], s_shift[k + 2]), 0.f);
            v.w = fmaxf(fmaf(v.w, s_scale[k + 3], s_shift[k + 3]), 0.f);
        }
        __half2 h01 = __floats2half2_rn(v.x, v.y);
        __half2 h23 = __floats2half2_rn(v.z, v.w);
        ull pk = (ull)(*reinterpret_cast<uint32_t*>(&h01)) |
                 ((ull)(*reinterpret_cast<uint32_t*>(&h23)) << 32);
        *reinterpret_cast<ull*>(&As[r * KS + k]) = pk;
    }

    // ---- B tile = W^T: Bs[n][k] = W[k][n] ----
    for (int idx = t; idx < K * 64; idx += 256) {
        int k = idx >> 6;
        int n = idx & 63;
        Bs[n * KS + k] = __float2half_rn(W[idx]);
    }
    __syncthreads();

    float acc[8][4];
#pragma unroll
    for (int nb = 0; nb < 8; nb++)
#pragma unroll
        for (int j = 0; j < 4; j++) acc[nb][j] = 0.f;

    uint32_t as_base = smem_u32(As);
    uint32_t bs_base = smem_u32(Bs);

    uint32_t a_row = wid * 16 + (lane & 15);
    uint32_t a_addr0 = as_base + (a_row * KS + (lane >> 4) * 8) * 2;
    uint32_t b_n = (lane & 7) + ((lane >> 4) & 1) * 8;
    uint32_t b_k = ((lane >> 3) & 1) * 8;
    uint32_t b_addr0 = bs_base + (b_n * KS + b_k) * 2;

#pragma unroll
    for (int ks = 0; ks < K / 16; ks++) {
        uint32_t a0, a1, a2, a3;
        ldmat_x4(a0, a1, a2, a3, a_addr0 + ks * 32);
#pragma unroll
        for (int nb2 = 0; nb2 < 4; nb2++) {
            uint32_t b0, b1, b2, b3;
            ldmat_x4(b0, b1, b2, b3, b_addr0 + (nb2 * 16 * KS + ks * 16) * 2);
            mma_16816(acc[nb2 * 2 + 0][0], acc[nb2 * 2 + 0][1], acc[nb2 * 2 + 0][2], acc[nb2 * 2 + 0][3],
                      a0, a1, a2, a3, b0, b1);
            mma_16816(acc[nb2 * 2 + 1][0], acc[nb2 * 2 + 1][1], acc[nb2 * 2 + 1][2], acc[nb2 * 2 + 1][3],
                      a0, a1, a2, a3, b2, b3);
        }
    }

    int g = lane >> 2;
    int tq = lane & 3;
    int row0 = m0 + wid * 16 + g;
    int row1 = row0 + 8;
    if (row0 < NN) {
        float di = g_dinv[row0];
#pragma unroll
        for (int nb = 0; nb < 8; nb++)
            C[(size_t)row0 * 32 + nb * 4 + tq] = __floats2half2_rn(acc[nb][0] * di, acc[nb][1] * di);
    }
    if (row1 < NN) {
        float di = g_dinv[row1];
#pragma unroll
        for (int nb = 0; nb < 8; nb++)
            C[(size_t)row1 * 32 + nb * 4 + tq] = __floats2half2_rn(acc[nb][2] * di, acc[nb][3] * di);
    }

    // ---- fused CSR fill (independent; overlaps other blocks' MMA) ----
    if (DO_FILL) {
        int stride = gridDim.x * 256;
        for (int e = blockIdx.x * 256 + t; e < EE; e += stride)
            g_csr[g_offcnt[dst[e]].x + g_rank[e]] = src[e];
    }
}

// ---------------- aggregation: quarter-warp per node + BN stats ----------------
// 8 lanes x uint4 (16B) cover the full 128B fp16 row; 4 independent node streams per warp
// (gather/index instructions per edge halved, MLP doubled). Unroll-4 groups summed with a
// 2-level fp16 pairwise tree (__hadd2), then one fp32 packed accumulate. Stats/epilogue
// fully packed via add.rn.f32x2 / fma.rn.f32x2.
__global__ __launch_bounds__(256, 4)
void aggstats_kernel(const __half2* __restrict__ h, const float* __restrict__ bias,
                     float* __restrict__ out, int layer) {
    __shared__ float s_sum[64], s_sq[64];
    int t = threadIdx.x;
    if (t < 64) { s_sum[t] = 0.f; s_sq[t] = 0.f; }
    __syncthreads();
    int c8 = t & 7;                                   // channels 8*c8 .. 8*c8+7
    int qId = (blockIdx.x * blockDim.x + t) >> 3;     // global quarter-warp id
    int totalQ = (gridDim.x * blockDim.x) >> 3;
    const uint4* h8 = reinterpret_cast<const uint4*>(h);   // 8 uint4 per row
    const ulonglong2* bp = reinterpret_cast<const ulonglong2*>(bias);  // 16 entries
    ulonglong2 bA = bp[c8 * 2 + 0];
    ulonglong2 bB = bp[c8 * 2 + 1];
    ull sm0 = 0, sm1 = 0, sm2 = 0, sm3 = 0;
    ull sq0 = 0, sq1 = 0, sq2 = 0, sq3 = 0;

    for (int i = qId; i < NN; i += totalQ) {
        uint2 oc = g_offcnt[i];
        int e0 = (int)oc.x;
        int e1 = e0 + (int)oc.y;
        float di = rsqrtf((float)(oc.y + 1u));
        float2 dif = make_float2(di, di);
        ull di2 = *reinterpret_cast<ull*>(&dif);
        uint4 sv = h8[(unsigned)i * 8u + c8];          // self-loop (pre-scaled)
        ull a0 = cvt2(sv.x), a1 = cvt2(sv.y), a2 = cvt2(sv.z), a3 = cvt2(sv.w);
        int j = e0;
        for (; j + 3 < e1; j += 4) {
            int s0 = g_csr[j], s1 = g_csr[j + 1], s2 = g_csr[j + 2], s3 = g_csr[j + 3];
            uint4 v0 = h8[(unsigned)s0 * 8u + c8];
            uint4 v1 = h8[(unsigned)s1 * 8u + c8];
            uint4 v2 = h8[(unsigned)s2 * 8u + c8];
            uint4 v3 = h8[(unsigned)s3 * 8u + c8];
            uint32_t w0 = hadd2u(hadd2u(v0.x, v1.x), hadd2u(v2.x, v3.x));
            uint32_t w1 = hadd2u(hadd2u(v0.y, v1.y), hadd2u(v2.y, v3.y));
            uint32_t w2 = hadd2u(hadd2u(v0.z, v1.z), hadd2u(v2.z, v3.z));
            uint32_t w3 = hadd2u(hadd2u(v0.w, v1.w), hadd2u(v2.w, v3.w));
            a0 = add2(a0, cvt2(w0));
            a1 = add2(a1, cvt2(w1));
            a2 = add2(a2, cvt2(w2));
            a3 = add2(a3, cvt2(w3));
        }
        for (; j < e1; j++) {
            uint4 v = h8[(unsigned)g_csr[j] * 8u + c8];
            a0 = add2(a0, cvt2(v.x));
            a1 = add2(a1, cvt2(v.y));
            a2 = add2(a2, cvt2(v.z));
            a3 = add2(a3, cvt2(v.w));
        }
        ull o0 = fma2(a0, di2, bA.x);
        ull o1 = fma2(a1, di2, bA.y);
        ull o2 = fma2(a2, di2, bB.x);
        ull o3 = fma2(a3, di2, bB.y);
        ulonglong2* o16 = reinterpret_cast<ulonglong2*>(out);
        o16[(size_t)i * 16 + 2 * c8 + 0] = make_ulonglong2(o0, o1);
        o16[(size_t)i * 16 + 2 * c8 + 1] = make_ulonglong2(o2, o3);
        sm0 = add2(sm0, o0); sq0 = fma2(o0, o0, sq0);
        sm1 = add2(sm1, o1); sq1 = fma2(o1, o1, sq1);
        sm2 = add2(sm2, o2); sq2 = fma2(o2, o2, sq2);
        sm3 = add2(sm3, o3); sq3 = fma2(o3, o3, sq3);
    }
    // unpack + shared reduction (8 sum + 8 sq atomics per thread, once)
    {
        float2 f;
        f = *reinterpret_cast<float2*>(&sm0);
        atomicAdd(&s_sum[c8 * 8 + 0], f.x); atomicAdd(&s_sum[c8 * 8 + 1], f.y);
        f = *reinterpret_cast<float2*>(&sm1);
        atomicAdd(&s_sum[c8 * 8 + 2], f.x); atomicAdd(&s_sum[c8 * 8 + 3], f.y);
        f = *reinterpret_cast<float2*>(&sm2);
        atomicAdd(&s_sum[c8 * 8 + 4], f.x); atomicAdd(&s_sum[c8 * 8 + 5], f.y);
        f = *reinterpret_cast<float2*>(&sm3);
        atomicAdd(&s_sum[c8 * 8 + 6], f.x); atomicAdd(&s_sum[c8 * 8 + 7], f.y);
        f = *reinterpret_cast<float2*>(&sq0);
        atomicAdd(&s_sq[c8 * 8 + 0], f.x); atomicAdd(&s_sq[c8 * 8 + 1], f.y);
        f = *reinterpret_cast<float2*>(&sq1);
        atomicAdd(&s_sq[c8 * 8 + 2], f.x); atomicAdd(&s_sq[c8 * 8 + 3], f.y);
        f = *reinterpret_cast<float2*>(&sq2);
        atomicAdd(&s_sq[c8 * 8 + 4], f.x); atomicAdd(&s_sq[c8 * 8 + 5], f.y);
        f = *reinterpret_cast<float2*>(&sq3);
        atomicAdd(&s_sq[c8 * 8 + 6], f.x); atomicAdd(&s_sq[c8 * 8 + 7], f.y);
    }
    __syncthreads();
    if (t < 64) {
        atomicAdd(&g_sum[layer][t], s_sum[t]);
        atomicAdd(&g_sq[layer][t], s_sq[t]);
    }
}

// BN apply with in-block prep: scale/shift from g_sum[1]/g_sq[1]
__global__ void bnapply_kernel(const float* __restrict__ v,
                               const float* __restrict__ gamma, const float* __restrict__ beta,
                               float* __restrict__ out) {
    __shared__ float sc[64], sf[64];
    int t = threadIdx.x;
    if (t < 64) {
        float m   = g_sum[1][t] * (1.0f / NN);
        float var = g_sq[1][t] * (1.0f / NN) - m * m;
        float s   = gamma[t] * rsqrtf(var + BN_EPS);
        sc[t] = s;
        sf[t] = beta[t] - m * s;
    }
    __syncthreads();
    int idx = blockIdx.x * blockDim.x + t;
    if (idx >= NN * 16) return;
    float4 x = reinterpret_cast<const float4*>(v)[idx];
    int c = (idx & 15) * 4;
    x.x = fmaxf(fmaf(x.x, sc[c + 0], sf[c + 0]), 0.f);
    x.y = fmaxf(fmaf(x.y, sc[c + 1], sf[c + 1]), 0.f);
    x.z = fmaxf(fmaf(x.z, sc[c + 2], sf[c + 2]), 0.f);
    x.w = fmaxf(fmaf(x.w, sc[c + 3], sf[c + 3]), 0.f);
    reinterpret_cast<float4*>(out)[idx] = x;
}

// ---------------- launch ----------------
extern "C" void kernel_launch(void* const* d_in, const int* in_sizes, int n_in,
                              void* d_out, int out_size) {
    const float* x   = (const float*)d_in[0];
    const int*   ei  = (const int*)d_in[1];
    const float* W1  = (const float*)d_in[2];
    const float* b1  = (const float*)d_in[3];
    const float* g1  = (const float*)d_in[4];
    const float* bt1 = (const float*)d_in[5];
    const float* W2  = (const float*)d_in[6];
    const float* b2  = (const float*)d_in[7];
    const float* g2  = (const float*)d_in[8];
    const float* bt2 = (const float*)d_in[9];
    float* out = (float*)d_out;

    const int* src = ei;
    const int* dst = ei + EE;

    __half2* hP = nullptr;
    float* aggP = nullptr;
    cudaGetSymbolAddress((void**)&hP, g_h);
    cudaGetSymbolAddress((void**)&aggP, g_agg);

    const int SMEM1 = 512 + 128 * (INF + 8) * 2 + 64 * (INF + 8) * 2;  // 52736
    const int SMEM2 = 512 + 128 * (HH + 8) * 2 + 64 * (HH + 8) * 2;    // 28160

    cudaFuncSetAttribute(mma_gemm_kernel<INF, 0, 1>,
                         cudaFuncAttributeMaxDynamicSharedMemorySize, SMEM1);
    cudaFuncSetAttribute(mma_gemm_kernel<HH, 1, 0>,
                         cudaFuncAttributeMaxDynamicSharedMemorySize, SMEM2);

    // fused hist + scan (device-wide barrier inside; 98 blocks = single wave)
    build_kernel<<<NB_BUILD, 1024>>>(dst);

    // ---- layer 1 (CSR fill fused into GEMM1) ----
    mma_gemm_kernel<INF, 0, 1><<<(NN + 127) / 128, 256, SMEM1>>>(x, W1, hP, nullptr, nullptr, src, dst);
    aggstats_kernel<<<AGG_BLOCKS, 256>>>(hP, b1, aggP, 0);

    // ---- layer 2: BN(layer1)+ReLU fused into A-tile load ----
    mma_gemm_kernel<HH, 1, 0><<<(NN + 127) / 128, 256, SMEM2>>>(aggP, W2, hP, g1, bt1, nullptr, nullptr);
    aggstats_kernel<<<AGG_BLOCKS, 256>>>(hP, b2, aggP, 1);
    bnapply_kernel<<<(NN * 16 + 255) / 256, 256>>>(aggP, g2, bt2, out);
}

// round 17
// speedup vs baseline: 1.1423x; 1.1423x over previous
#include <cuda_runtime.h>
#include <cuda_bf16.h>
#include <cuda_fp16.h>
#include <math.h>
#include <stdint.h>

#define NN 100000
#define EE 1000000
#define INF 128
#define HH 64
#define BN_EPS 1e-5f
#define NB_BUILD 98
#define AGG_BLOCKS 888

typedef unsigned long long ull;

// ---------------- scratch (device globals, no runtime alloc) ----------------
// Invariant: g_indeg is all-zero at every kernel_launch entry (zero-initialized at
// module load; build kernel re-zeros it after use on every execution).
// g_bar1 / g_ticket / g_flag are MONOTONIC (generation = value/NB_BUILD).
__device__ int   g_indeg[NN];
__device__ uint2 g_offcnt[NN];     // {csr offset, indegree}
__device__ int   g_rank[EE];
__device__ int   g_csr[EE];
__device__ float g_dinv[NN];
__device__ int   g_bsum[NB_BUILD];
__device__ int   g_boff[NB_BUILD];
__device__ int   g_bar1;
__device__ int   g_ticket;
__device__ int   g_flag;
__device__ float g_sum[2][HH];
__device__ float g_sq[2][HH];

__device__ __half2 g_h[(size_t)NN * 32];   // GEMM output (fp16 pairs), pre-scaled by dinv[row]
__device__ float   g_agg[(size_t)NN * HH]; // aggregation output (pre-BN, fp32)

// packed dual-fp32 add (Blackwell; ptxas never emits this from C++)
__device__ __forceinline__ ull add2(ull a, ull b) {
    ull d;
    asm("add.rn.f32x2 %0, %1, %2;" : "=l"(d) : "l"(a), "l"(b));
    return d;
}

// ---------------- fused graph build: hist + device barrier + scan ----------------
__global__ __launch_bounds__(1024, 1)
void build_kernel(const int* __restrict__ dst) {
    __shared__ int sh[1024];
    __shared__ int sh_tgt;
    __shared__ int sh_gen;
    __shared__ int amLast;
    int t = threadIdx.x;
    int b = blockIdx.x;

    if (b == 0 && t < 2 * HH) {
        ((float*)g_sum)[t] = 0.f;
        ((float*)g_sq)[t]  = 0.f;
    }

    // ---- phase 1: histogram + per-edge rank (grid-stride) ----
    for (int e = b * 1024 + t; e < EE; e += NB_BUILD * 1024)
        g_rank[e] = atomicAdd(&g_indeg[dst[e]], 1);

    // ---- device-wide barrier (monotonic generation counter) ----
    __syncthreads();
    if (t == 0) {
        __threadfence();
        int my = atomicAdd(&g_bar1, 1);
        sh_tgt = (my / NB_BUILD + 1) * NB_BUILD;
    }
    __syncthreads();
    if (t == 0) {
        while (atomicAdd(&g_bar1, 0) < sh_tgt) {}
    }
    __syncthreads();

    // ---- phase 2: block-local inclusive scan of indeg ----
    int idx = b * 1024 + t;
    int v = (idx < NN) ? g_indeg[idx] : 0;
    sh[t] = v;
    __syncthreads();
    for (int o = 1; o < 1024; o <<= 1) {
        int a = (t >= o) ? sh[t - o] : 0;
        __syncthreads();
        sh[t] += a;
        __syncthreads();
    }
    int incl = sh[t];
    if (t == 1023) {
        g_bsum[b] = incl;
        __threadfence();
        int my = atomicAdd(&g_ticket, 1);
        amLast = ((my % NB_BUILD) == NB_BUILD - 1);
        sh_gen = my / NB_BUILD;
    }
    __syncthreads();
    int gen = sh_gen;
    if (amLast) {
        int bv = (t < NB_BUILD) ? g_bsum[t] : 0;
        sh[t] = (t < 128) ? bv : 0;
        __syncthreads();
        for (int o = 1; o < 128; o <<= 1) {
            int a = (t >= o && t < 128) ? sh[t - o] : 0;
            __syncthreads();
            if (t < 128) sh[t] += a;
            __syncthreads();
        }
        if (t < NB_BUILD) g_boff[t] = sh[t] - bv;
        __threadfence();
        if (t == 0) atomicAdd(&g_flag, 1);
    }
    if (t == 0) {
        while (atomicAdd(&g_flag, 0) < gen + 1) {}
    }
    __syncthreads();
    if (idx < NN) {
        int off = g_boff[b] + incl - v;
        g_offcnt[idx] = make_uint2((unsigned)off, (unsigned)v);
        g_dinv[idx] = rsqrtf((float)(v + 1));   // deg = indeg + self-loop (GEMM epilogue)
        g_indeg[idx] = 0;                        // self-clean for next call
    }
}

// ---------------- HMMA GEMM: A fragments loaded DIRECTLY from global ----------------
// m16n8k16 A-fragment (row-major): thread (g=lane>>2, tq=lane&3) holds
//   a0 = A[row g   ][k0..k0+1],  a1 = A[row g+8][k0..k0+1],
//   a2 = A[row g   ][k0+8..+9],  a3 = A[row g+8][k0+8..+9],   k0 = ks*16 + 2*tq.
// Loaded as float2 -> (BN+ReLU) -> half2. No A smem, no bulk-load barrier: the
// per-kstep LDG.64s overlap MMAs across warps/blocks. B = W^T stays in smem.

__device__ __forceinline__ uint32_t smem_u32(const void* p) {
    uint32_t a;
    asm("{ .reg .u64 t; cvta.to.shared.u64 t, %1; cvt.u32.u64 %0, t; }" : "=r"(a) : "l"(p));
    return a;
}

__device__ __forceinline__ void ldmat_x4(uint32_t& r0, uint32_t& r1, uint32_t& r2, uint32_t& r3,
                                         uint32_t addr) {
    asm volatile("ldmatrix.sync.aligned.m8n8.x4.shared.b16 {%0,%1,%2,%3}, [%4];"
                 : "=r"(r0), "=r"(r1), "=r"(r2), "=r"(r3) : "r"(addr));
}

__device__ __forceinline__ void mma_16816(float& c0, float& c1, float& c2, float& c3,
                                          uint32_t a0, uint32_t a1, uint32_t a2, uint32_t a3,
                                          uint32_t b0, uint32_t b1) {
    asm volatile("mma.sync.aligned.m16n8k16.row.col.f32.f16.f16.f32 "
                 "{%0,%1,%2,%3}, {%4,%5,%6,%7}, {%8,%9}, {%0,%1,%2,%3};"
                 : "+f"(c0), "+f"(c1), "+f"(c2), "+f"(c3)
                 : "r"(a0), "r"(a1), "r"(a2), "r"(a3), "r"(b0), "r"(b1));
}

__device__ __forceinline__ uint32_t pack_h2(float2 v) {
    __half2 h = __floats2half2_rn(v.x, v.y);
    return *reinterpret_cast<uint32_t*>(&h);
}

template <int K, int DO_BN, int DO_FILL>
__global__ __launch_bounds__(256, 4)
void mma_gemm_kernel(const float* __restrict__ A, const float* __restrict__ W,
                     __half2* __restrict__ C,
                     const float* __restrict__ gamma, const float* __restrict__ beta,
                     const int* __restrict__ src, const int* __restrict__ dst) {
    extern __shared__ char smem[];
    const int KS = K + 8;
    float* s_scale = (float*)(smem + 0);
    float* s_shift = (float*)(smem + 256);
    __half* Bs = (__half*)(smem + 512);

    int t = threadIdx.x;
    int wid = t >> 5;
    int lane = t & 31;
    int m0 = blockIdx.x * 128;

    if (DO_BN) {
        if (t < 64) {
            float m   = g_sum[0][t] * (1.0f / NN);
            float var = g_sq[0][t] * (1.0f / NN) - m * m;
            float sc  = gamma[t] * rsqrtf(var + BN_EPS);
            s_scale[t] = sc;
            s_shift[t] = beta[t] - m * sc;
        }
    }

    // ---- B tile = W^T: Bs[n][k] = W[k][n] ----
    for (int idx = t; idx < K * 64; idx += 256) {
        int k = idx >> 6;
        int n = idx & 63;
        Bs[n * KS + k] = __float2half_rn(W[idx]);
    }
    __syncthreads();

    float acc[8][4];
#pragma unroll
    for (int nb = 0; nb < 8; nb++)
#pragma unroll
        for (int j = 0; j < 4; j++) acc[nb][j] = 0.f;

    uint32_t bs_base = smem_u32(Bs);
    uint32_t b_n = (lane & 7) + ((lane >> 4) & 1) * 8;
    uint32_t b_k = ((lane >> 3) & 1) * 8;
    uint32_t b_addr0 = bs_base + (b_n * KS + b_k) * 2;

    int g = lane >> 2;
    int tq = lane & 3;
    int row0 = m0 + wid * 16 + g;
    int row1 = row0 + 8;
    bool v0 = row0 < NN, v1 = row1 < NN;
    const float* A0 = A + (size_t)row0 * K;
    const float* A1 = A + (size_t)row1 * K;

#pragma unroll
    for (int ks = 0; ks < K / 16; ks++) {
        int k0 = ks * 16 + 2 * tq;
        int k1 = k0 + 8;
        float2 x00 = make_float2(0.f, 0.f), x01 = x00, x10 = x00, x11 = x00;
        if (v0) {
            x00 = *reinterpret_cast<const float2*>(A0 + k0);
            x01 = *reinterpret_cast<const float2*>(A0 + k1);
        }
        if (v1) {
            x10 = *reinterpret_cast<const float2*>(A1 + k0);
            x11 = *reinterpret_cast<const float2*>(A1 + k1);
        }
        if (DO_BN) {
            float2 sc0 = *reinterpret_cast<const float2*>(s_scale + k0);
            float2 sf0 = *reinterpret_cast<const float2*>(s_shift + k0);
            float2 sc1 = *reinterpret_cast<const float2*>(s_scale + k1);
            float2 sf1 = *reinterpret_cast<const float2*>(s_shift + k1);
            x00.x = fmaxf(fmaf(x00.x, sc0.x, sf0.x), 0.f);
            x00.y = fmaxf(fmaf(x00.y, sc0.y, sf0.y), 0.f);
            x10.x = fmaxf(fmaf(x10.x, sc0.x, sf0.x), 0.f);
            x10.y = fmaxf(fmaf(x10.y, sc0.y, sf0.y), 0.f);
            x01.x = fmaxf(fmaf(x01.x, sc1.x, sf1.x), 0.f);
            x01.y = fmaxf(fmaf(x01.y, sc1.y, sf1.y), 0.f);
            x11.x = fmaxf(fmaf(x11.x, sc1.x, sf1.x), 0.f);
            x11.y = fmaxf(fmaf(x11.y, sc1.y, sf1.y), 0.f);
        }
        uint32_t a0 = pack_h2(x00);
        uint32_t a1 = pack_h2(x10);
        uint32_t a2 = pack_h2(x01);
        uint32_t a3 = pack_h2(x11);
#pragma unroll
        for (int nb2 = 0; nb2 < 4; nb2++) {
            uint32_t b0, b1, b2, b3;
            ldmat_x4(b0, b1, b2, b3, b_addr0 + (nb2 * 16 * KS + ks * 16) * 2);
            mma_16816(acc[nb2 * 2 + 0][0], acc[nb2 * 2 + 0][1], acc[nb2 * 2 + 0][2], acc[nb2 * 2 + 0][3],
                      a0, a1, a2, a3, b0, b1);
            mma_16816(acc[nb2 * 2 + 1][0], acc[nb2 * 2 + 1][1], acc[nb2 * 2 + 1][2], acc[nb2 * 2 + 1][3],
                      a0, a1, a2, a3, b2, b3);
        }
    }

    if (v0) {
        float di = g_dinv[row0];
#pragma unroll
        for (int nb = 0; nb < 8; nb++)
            C[(size_t)row0 * 32 + nb * 4 + tq] = __floats2half2_rn(acc[nb][0] * di, acc[nb][1] * di);
    }
    if (v1) {
        float di = g_dinv[row1];
#pragma unroll
        for (int nb = 0; nb < 8; nb++)
            C[(size_t)row1 * 32 + nb * 4 + tq] = __floats2half2_rn(acc[nb][2] * di, acc[nb][3] * di);
    }

    // ---- fused CSR fill (independent; overlaps other blocks' MMA) ----
    if (DO_FILL) {
        int stride = gridDim.x * 256;
        for (int e = blockIdx.x * 256 + t; e < EE; e += stride)
            g_csr[g_offcnt[dst[e]].x + g_rank[e]] = src[e];
    }
}

// ---------------- aggregation: half-warp per node, fp16 gather, f32x2 accum + BN stats ----------------
// (R14 version — best measured agg)
__global__ __launch_bounds__(256, 6)
void aggstats_kernel(const __half2* __restrict__ h, const float* __restrict__ bias,
                     float* __restrict__ out, int layer) {
    __shared__ float s_sum[64], s_sq[64];
    int t = threadIdx.x;
    if (t < 64) { s_sum[t] = 0.f; s_sq[t] = 0.f; }
    __syncthreads();
    int c4 = t & 15;
    int hwId = (blockIdx.x * blockDim.x + t) >> 4;
    int totalHW = (gridDim.x * blockDim.x) >> 4;
    const uint2* h4 = reinterpret_cast<const uint2*>(h);
    float4 b4 = reinterpret_cast<const float4*>(bias)[c4];
    float sm0 = 0.f, sm1 = 0.f, sm2 = 0.f, sm3 = 0.f;
    float sq0 = 0.f, sq1 = 0.f, sq2 = 0.f, sq3 = 0.f;

    for (int i = hwId; i < NN; i += totalHW) {
        uint2 oc = g_offcnt[i];
        int e0 = (int)oc.x;
        int e1 = e0 + (int)oc.y;
        float di = rsqrtf((float)(oc.y + 1u));
        uint2 sv = h4[(unsigned)i * 16u + c4];
        float2 f0 = __half22float2(*reinterpret_cast<__half2*>(&sv.x));
        float2 f1 = __half22float2(*reinterpret_cast<__half2*>(&sv.y));
        ulonglong2 a2;
        a2.x = *reinterpret_cast<ull*>(&f0);
        a2.y = *reinterpret_cast<ull*>(&f1);
        int j = e0;
        for (; j + 3 < e1; j += 4) {
            int s0 = g_csr[j], s1 = g_csr[j + 1], s2 = g_csr[j + 2], s3 = g_csr[j + 3];
            uint2 v0 = h4[(unsigned)s0 * 16u + c4];
            uint2 v1 = h4[(unsigned)s1 * 16u + c4];
            uint2 v2 = h4[(unsigned)s2 * 16u + c4];
            uint2 v3 = h4[(unsigned)s3 * 16u + c4];
            float2 p0 = __half22float2(*reinterpret_cast<__half2*>(&v0.x));
            float2 p1 = __half22float2(*reinterpret_cast<__half2*>(&v0.y));
            float2 q0 = __half22float2(*reinterpret_cast<__half2*>(&v1.x));
            float2 q1 = __half22float2(*reinterpret_cast<__half2*>(&v1.y));
            float2 r0 = __half22float2(*reinterpret_cast<__half2*>(&v2.x));
            float2 r1 = __half22float2(*reinterpret_cast<__half2*>(&v2.y));
            float2 w0 = __half22float2(*reinterpret_cast<__half2*>(&v3.x));
            float2 w1 = __half22float2(*reinterpret_cast<__half2*>(&v3.y));
            ull u0x = add2(*reinterpret_cast<ull*>(&p0), *reinterpret_cast<ull*>(&q0));
            ull u0y = add2(*reinterpret_cast<ull*>(&p1), *reinterpret_cast<ull*>(&q1));
            ull u2x = add2(*reinterpret_cast<ull*>(&r0), *reinterpret_cast<ull*>(&w0));
            ull u2y = add2(*reinterpret_cast<ull*>(&r1), *reinterpret_cast<ull*>(&w1));
            a2.x = add2(a2.x, add2(u0x, u2x));
            a2.y = add2(a2.y, add2(u0y, u2y));
        }
        for (; j < e1; j++) {
            uint2 v = h4[(unsigned)g_csr[j] * 16u + c4];
            float2 p0 = __half22float2(*reinterpret_cast<__half2*>(&v.x));
            float2 p1 = __half22float2(*reinterpret_cast<__half2*>(&v.y));
            a2.x = add2(a2.x, *reinterpret_cast<ull*>(&p0));
            a2.y = add2(a2.y, *reinterpret_cast<ull*>(&p1));
        }
        float2 acc0 = *reinterpret_cast<float2*>(&a2.x);
        float2 acc1 = *reinterpret_cast<float2*>(&a2.y);
        float4 o;
        o.x = fmaf(acc0.x, di, b4.x);
        o.y = fmaf(acc0.y, di, b4.y);
        o.z = fmaf(acc1.x, di, b4.z);
        o.w = fmaf(acc1.y, di, b4.w);
        reinterpret_cast<float4*>(out)[(unsigned)i * 16u + c4] = o;
        sm0 += o.x; sq0 += o.x * o.x;
        sm1 += o.y; sq1 += o.y * o.y;
        sm2 += o.z; sq2 += o.z * o.z;
        sm3 += o.w; sq3 += o.w * o.w;
    }
    atomicAdd(&s_sum[c4 * 4 + 0], sm0);
    atomicAdd(&s_sum[c4 * 4 + 1], sm1);
    atomicAdd(&s_sum[c4 * 4 + 2], sm2);
    atomicAdd(&s_sum[c4 * 4 + 3], sm3);
    atomicAdd(&s_sq [c4 * 4 + 0], sq0);
    atomicAdd(&s_sq [c4 * 4 + 1], sq1);
    atomicAdd(&s_sq [c4 * 4 + 2], sq2);
    atomicAdd(&s_sq [c4 * 4 + 3], sq3);
    __syncthreads();
    if (t < 64) {
        atomicAdd(&g_sum[layer][t], s_sum[t]);
        atomicAdd(&g_sq[layer][t], s_sq[t]);
    }
}

// BN apply with in-block prep: scale/shift from g_sum[1]/g_sq[1]
__global__ void bnapply_kernel(const float* __restrict__ v,
                               const float* __restrict__ gamma, const float* __restrict__ beta,
                               float* __restrict__ out) {
    __shared__ float sc[64], sf[64];
    int t = threadIdx.x;
    if (t < 64) {
        float m   = g_sum[1][t] * (1.0f / NN);
        float var = g_sq[1][t] * (1.0f / NN) - m * m;
        float s   = gamma[t] * rsqrtf(var + BN_EPS);
        sc[t] = s;
        sf[t] = beta[t] - m * s;
    }
    __syncthreads();
    int idx = blockIdx.x * blockDim.x + t;
    if (idx >= NN * 16) return;
    float4 x = reinterpret_cast<const float4*>(v)[idx];
    int c = (idx & 15) * 4;
    x.x = fmaxf(fmaf(x.x, sc[c + 0], sf[c + 0]), 0.f);
    x.y = fmaxf(fmaf(x.y, sc[c + 1], sf[c + 1]), 0.f);
    x.z = fmaxf(fmaf(x.z, sc[c + 2], sf[c + 2]), 0.f);
    x.w = fmaxf(fmaf(x.w, sc[c + 3], sf[c + 3]), 0.f);
    reinterpret_cast<float4*>(out)[idx] = x;
}

// ---------------- launch ----------------
extern "C" void kernel_launch(void* const* d_in, const int* in_sizes, int n_in,
                              void* d_out, int out_size) {
    const float* x   = (const float*)d_in[0];
    const int*   ei  = (const int*)d_in[1];
    const float* W1  = (const float*)d_in[2];
    const float* b1  = (const float*)d_in[3];
    const float* g1  = (const float*)d_in[4];
    const float* bt1 = (const float*)d_in[5];
    const float* W2  = (const float*)d_in[6];
    const float* b2  = (const float*)d_in[7];
    const float* g2  = (const float*)d_in[8];
    const float* bt2 = (const float*)d_in[9];
    float* out = (float*)d_out;

    const int* src = ei;
    const int* dst = ei + EE;

    __half2* hP = nullptr;
    float* aggP = nullptr;
    cudaGetSymbolAddress((void**)&hP, g_h);
    cudaGetSymbolAddress((void**)&aggP, g_agg);

    const int SMEM1 = 512 + 64 * (INF + 8) * 2;  // 17920 (B tile only)
    const int SMEM2 = 512 + 64 * (HH + 8) * 2;   // 9728

    cudaFuncSetAttribute(mma_gemm_kernel<INF, 0, 1>,
                         cudaFuncAttributeMaxDynamicSharedMemorySize, SMEM1);
    cudaFuncSetAttribute(mma_gemm_kernel<HH, 1, 0>,
                         cudaFuncAttributeMaxDynamicSharedMemorySize, SMEM2);

    // fused hist + scan (device-wide barrier inside; 98 blocks = single wave)
    build_kernel<<<NB_BUILD, 1024>>>(dst);

    // ---- layer 1 (CSR fill fused into GEMM1) ----
    mma_gemm_kernel<INF, 0, 1><<<(NN + 127) / 128, 256, SMEM1>>>(x, W1, hP, nullptr, nullptr, src, dst);
    aggstats_kernel<<<AGG_BLOCKS, 256>>>(hP, b1, aggP, 0);

    // ---- layer 2: BN(layer1)+ReLU fused into A-fragment load ----
    mma_gemm_kernel<HH, 1, 0><<<(NN + 127) / 128, 256, SMEM2>>>(aggP, W2, hP, g1, bt1, nullptr, nullptr);
    aggstats_kernel<<<AGG_BLOCKS, 256>>>(hP, b2, aggP, 1);
    bnapply_kernel<<<(NN * 16 + 255) / 256, 256>>>(aggP, g2, bt2, out);
}